// round 2
// baseline (speedup 1.0000x reference)
#include <cuda_runtime.h>

#define C_    16
#define H_    512
#define W_    512
#define HW_   (H_ * W_)
#define HID_  128
#define FEAT_ 80
#define NSTEP 8

// Ping-pong scratch for intermediate states (32 MB). Allocation-free rule:
// __device__ globals are the sanctioned scratch mechanism.
__device__ float g_buf[2][C_ * HW_];

// smem: W1 (80x128) + W2 (128x16)  -> 49152 B exactly (default dynamic limit,
// no cudaFuncSetAttribute needed). Biases stay in global (uniform L1 reads).
#define SMEM_FLOATS (FEAT_ * HID_ + HID_ * C_)
#define SMEM_BYTES  (SMEM_FLOATS * 4)

__global__ __launch_bounds__(256, 2)
void slime_step(const float* __restrict__ src, float* __restrict__ dst,
                const float* __restrict__ gW1, const float* __restrict__ gb1,
                const float* __restrict__ gW2, const float* __restrict__ gb2)
{
    extern __shared__ float sm[];
    float* w1s = sm;                      // [80][128] row-major (k-major, j contiguous)
    float* w2s = sm + FEAT_ * HID_;       // [128][16] row-major (j-major, c contiguous)

    const int tid = threadIdx.x;
    for (int i = tid; i < FEAT_ * HID_; i += 256) w1s[i] = gW1[i];
    for (int i = tid; i < HID_ * C_;  i += 256)   w2s[i] = gW2[i];
    __syncthreads();

    const int p = blockIdx.x * 256 + tid;     // pixel index in [0, HW)
    const int y = p >> 9;
    const int x = p & (W_ - 1);

    // Reference quirk: minus-neighbor clamps at 0, plus-neighbor WRAPS to 0.
    const int yu = (y == 0)      ? 0 : y - 1;
    const int yd = (y == H_ - 1) ? 0 : y + 1;
    const int xl = (x == 0)      ? 0 : x - 1;
    const int xr = (x == W_ - 1) ? 0 : x + 1;

    const int pc = y  * W_ + x;
    const int pu = yu * W_ + x;
    const int pd = yd * W_ + x;
    const int pl = y  * W_ + xl;
    const int pr = y  * W_ + xr;

    // Gather 80 features into registers.
    // Feature order must match concat([center, up, down, left, right]).
    float f[FEAT_];
#pragma unroll
    for (int c = 0; c < C_; c++) {
        const float* plane = src + c * HW_;
        f[c]          = plane[pc];
        f[16 + c]     = plane[pu];
        f[32 + c]     = plane[pd];
        f[48 + c]     = plane[pl];
        f[64 + c]     = plane[pr];
    }

    float delta[C_];
#pragma unroll
    for (int c = 0; c < C_; c++) delta[c] = __ldg(&gb2[c]);

    // Hidden units 4 at a time: vectorized along j (W1 rows are j-contiguous,
    // W2 rows are c-contiguous) -> float4 broadcast LDS, FMA:LDS ~ 4:1.
#pragma unroll 1
    for (int jq = 0; jq < HID_ / 4; jq++) {
        float4 acc = __ldg((const float4*)&gb1[4 * jq]);
#pragma unroll
        for (int k = 0; k < FEAT_; k++) {
            const float4 wv = *(const float4*)&w1s[k * HID_ + 4 * jq];
            acc.x = fmaf(f[k], wv.x, acc.x);
            acc.y = fmaf(f[k], wv.y, acc.y);
            acc.z = fmaf(f[k], wv.z, acc.z);
            acc.w = fmaf(f[k], wv.w, acc.w);
        }
        const float h0 = fmaxf(acc.x, 0.f);
        const float h1 = fmaxf(acc.y, 0.f);
        const float h2 = fmaxf(acc.z, 0.f);
        const float h3 = fmaxf(acc.w, 0.f);

        const float* w2r = &w2s[(4 * jq) * C_];
#pragma unroll
        for (int c4 = 0; c4 < C_ / 4; c4++) {
            const float4 w0  = *(const float4*)&w2r[0 * C_ + 4 * c4];
            const float4 w1v = *(const float4*)&w2r[1 * C_ + 4 * c4];
            const float4 w2v = *(const float4*)&w2r[2 * C_ + 4 * c4];
            const float4 w3  = *(const float4*)&w2r[3 * C_ + 4 * c4];
            delta[4 * c4 + 0] = fmaf(h0, w0.x, fmaf(h1, w1v.x, fmaf(h2, w2v.x, fmaf(h3, w3.x, delta[4 * c4 + 0]))));
            delta[4 * c4 + 1] = fmaf(h0, w0.y, fmaf(h1, w1v.y, fmaf(h2, w2v.y, fmaf(h3, w3.y, delta[4 * c4 + 1]))));
            delta[4 * c4 + 2] = fmaf(h0, w0.z, fmaf(h1, w1v.z, fmaf(h2, w2v.z, fmaf(h3, w3.z, delta[4 * c4 + 2]))));
            delta[4 * c4 + 3] = fmaf(h0, w0.w, fmaf(h1, w1v.w, fmaf(h2, w2v.w, fmaf(h3, w3.w, delta[4 * c4 + 3]))));
        }
    }

    // Channel 0: snapshot restore (delta not applied).
    dst[pc] = f[0];
#pragma unroll
    for (int c = 1; c < C_; c++)
        dst[c * HW_ + pc] = f[c] + delta[c];
}

extern "C" void kernel_launch(void* const* d_in, const int* in_sizes, int n_in,
                              void* d_out, int out_size)
{
    const float* state = (const float*)d_in[0];
    const float* W1    = (const float*)d_in[1];
    const float* b1    = (const float*)d_in[2];
    const float* W2    = (const float*)d_in[3];
    const float* b2    = (const float*)d_in[4];
    float* out = (float*)d_out;

    void* sym = nullptr;
    cudaGetSymbolAddress(&sym, g_buf);
    float* buf0 = (float*)sym;
    float* buf1 = buf0 + C_ * HW_;

    const float* src = state;
    for (int s = 0; s < NSTEP; s++) {
        float* dst = (s == NSTEP - 1) ? out : ((s & 1) ? buf1 : buf0);
        slime_step<<<HW_ / 256, 256, SMEM_BYTES>>>(src, dst, W1, b1, W2, b2);
        src = dst;
    }
}

// round 3
// speedup vs baseline: 1.0056x; 1.0056x over previous
#include <cuda_runtime.h>

#define C_    16
#define H_    512
#define W_    512
#define HW_   (H_ * W_)
#define HID_  128
#define FEAT_ 80
#define NSTEP 8

// Ping-pong scratch for intermediate states (32 MB).
__device__ float g_buf[2][C_ * HW_];

// Duplicated-pair weights in smem: W1d [80][128][2], W2d [128][16][2]
#define W1D_FLOATS (FEAT_ * HID_ * 2)
#define W2D_FLOATS (HID_ * C_ * 2)
#define SMEM_BYTES ((W1D_FLOATS + W2D_FLOATS) * 4)   // 98304 B

typedef unsigned long long u64;

__device__ __forceinline__ u64 pack2(float lo, float hi) {
    u64 r;
    asm("mov.b64 %0, {%1, %2};" : "=l"(r) : "f"(lo), "f"(hi));
    return r;
}
__device__ __forceinline__ void unpack2(u64 v, float& lo, float& hi) {
    asm("mov.b64 {%0, %1}, %2;" : "=f"(lo), "=f"(hi) : "l"(v));
}
__device__ __forceinline__ u64 ffma2(u64 a, u64 b, u64 c) {
    u64 d;
    asm("fma.rn.f32x2 %0, %1, %2, %3;" : "=l"(d) : "l"(a), "l"(b), "l"(c));
    return d;
}
__device__ __forceinline__ u64 relu2(u64 v) {
    float lo, hi;
    unpack2(v, lo, hi);
    return pack2(fmaxf(lo, 0.f), fmaxf(hi, 0.f));
}

__global__ __launch_bounds__(256, 1)
void slime_step(const float* __restrict__ src, float* __restrict__ dst,
                const float* __restrict__ gW1, const float* __restrict__ gb1,
                const float* __restrict__ gW2, const float* __restrict__ gb2)
{
    extern __shared__ float sm[];
    float* w1d = sm;                 // [k][j][2] duplicated pairs
    float* w2d = sm + W1D_FLOATS;    // [j][c][2] duplicated pairs

    const int tid = threadIdx.x;
    for (int i = tid; i < FEAT_ * HID_; i += 256) {
        const float w = gW1[i];
        w1d[2 * i] = w; w1d[2 * i + 1] = w;
    }
    for (int i = tid; i < HID_ * C_; i += 256) {
        const float w = gW2[i];
        w2d[2 * i] = w; w2d[2 * i + 1] = w;
    }
    __syncthreads();

    // One block per image row; thread handles pixels (x0, x0+256) of row y.
    const int y  = blockIdx.x;
    const int x0 = tid;          // 0..255  (x0+1 never wraps, x0-1 clamps at 0)
    const int x1 = tid + 256;    // 256..511 (x1-1 never clamps, x1+1 wraps at 511)

    const int yu = (y == 0)      ? 0 : y - 1;   // clamp low
    const int yd = (y == H_ - 1) ? 0 : y + 1;   // WRAP high (reference quirk)
    const int xl0 = (x0 == 0)      ? 0 : x0 - 1;
    const int xr0 = x0 + 1;
    const int xl1 = x1 - 1;
    const int xr1 = (x1 == W_ - 1) ? 0 : x1 + 1;

    const int rc = y  * W_;
    const int ru = yu * W_;
    const int rd = yd * W_;

    // Gather 80 feature pairs. Order: [center, up, down, left, right] x 16ch.
    u64 fp[FEAT_];
#pragma unroll
    for (int c = 0; c < C_; c++) {
        const float* pl = src + c * HW_;
        fp[c]          = pack2(pl[rc + x0],  pl[rc + x1]);
        fp[16 + c]     = pack2(pl[ru + x0],  pl[ru + x1]);
        fp[32 + c]     = pack2(pl[rd + x0],  pl[rd + x1]);
        fp[48 + c]     = pack2(pl[rc + xl0], pl[rc + xl1]);
        fp[64 + c]     = pack2(pl[rc + xr0], pl[rc + xr1]);
    }

    u64 delta[C_];
#pragma unroll
    for (int c = 0; c < C_; c++) {
        const float b = __ldg(&gb2[c]);
        delta[c] = pack2(b, b);
    }

#pragma unroll 1
    for (int jq = 0; jq < HID_ / 4; jq++) {
        const float4 bb = *(const float4*)&gb1[4 * jq];
        u64 a0 = pack2(bb.x, bb.x);
        u64 a1 = pack2(bb.y, bb.y);
        u64 a2 = pack2(bb.z, bb.z);
        u64 a3 = pack2(bb.w, bb.w);

        const float* wbase = w1d + (4 * jq) * 2;
#pragma unroll
        for (int k = 0; k < FEAT_; k++) {
            // 16B = dup'd pairs (w_j0,w_j0),(w_j1,w_j1); next 16B = j2,j3
            const ulonglong2 wab = *(const ulonglong2*)(wbase + k * (HID_ * 2));
            const ulonglong2 wcd = *(const ulonglong2*)(wbase + k * (HID_ * 2) + 4);
            a0 = ffma2(fp[k], wab.x, a0);
            a1 = ffma2(fp[k], wab.y, a1);
            a2 = ffma2(fp[k], wcd.x, a2);
            a3 = ffma2(fp[k], wcd.y, a3);
        }

        u64 h0 = relu2(a0);
        u64 h1 = relu2(a1);
        u64 h2 = relu2(a2);
        u64 h3 = relu2(a3);

        // Layer 2: delta[c] += h_j * w2[j][c] for the 4 j's of this jq.
        const float* w2r = w2d + (4 * jq) * (C_ * 2);
#pragma unroll
        for (int cc = 0; cc < C_ / 2; cc++) {
            const ulonglong2 q0 = *(const ulonglong2*)(w2r + 0 * (C_ * 2) + cc * 4);
            const ulonglong2 q1 = *(const ulonglong2*)(w2r + 1 * (C_ * 2) + cc * 4);
            const ulonglong2 q2 = *(const ulonglong2*)(w2r + 2 * (C_ * 2) + cc * 4);
            const ulonglong2 q3 = *(const ulonglong2*)(w2r + 3 * (C_ * 2) + cc * 4);
            u64 d0 = delta[2 * cc], d1 = delta[2 * cc + 1];
            d0 = ffma2(h0, q0.x, d0);  d1 = ffma2(h0, q0.y, d1);
            d0 = ffma2(h1, q1.x, d0);  d1 = ffma2(h1, q1.y, d1);
            d0 = ffma2(h2, q2.x, d0);  d1 = ffma2(h2, q2.y, d1);
            d0 = ffma2(h3, q3.x, d0);  d1 = ffma2(h3, q3.y, d1);
            delta[2 * cc] = d0; delta[2 * cc + 1] = d1;
        }
    }

    // Channel 0 snapshot restore: delta not applied.
    {
        float lo, hi;
        unpack2(fp[0], lo, hi);
        dst[rc + x0] = lo;
        dst[rc + x1] = hi;
    }
#pragma unroll
    for (int c = 1; c < C_; c++) {
        float fl, fh, dl, dh;
        unpack2(fp[c], fl, fh);
        unpack2(delta[c], dl, dh);
        dst[c * HW_ + rc + x0] = fl + dl;
        dst[c * HW_ + rc + x1] = fh + dh;
    }
}

extern "C" void kernel_launch(void* const* d_in, const int* in_sizes, int n_in,
                              void* d_out, int out_size)
{
    const float* state = (const float*)d_in[0];
    const float* W1    = (const float*)d_in[1];
    const float* b1    = (const float*)d_in[2];
    const float* W2    = (const float*)d_in[3];
    const float* b2    = (const float*)d_in[4];
    float* out = (float*)d_out;

    void* sym = nullptr;
    cudaGetSymbolAddress(&sym, g_buf);
    float* buf0 = (float*)sym;
    float* buf1 = buf0 + C_ * HW_;

    // Immediate-mode attribute set (not a stream op; capture-safe, idempotent).
    cudaFuncSetAttribute(slime_step, cudaFuncAttributeMaxDynamicSharedMemorySize, SMEM_BYTES);

    const float* src = state;
    for (int s = 0; s < NSTEP; s++) {
        float* dst = (s == NSTEP - 1) ? out : ((s & 1) ? buf1 : buf0);
        slime_step<<<H_, 256, SMEM_BYTES>>>(src, dst, W1, b1, W2, b2);
        src = dst;
    }
}